// round 14
// baseline (speedup 1.0000x reference)
#include <cuda_runtime.h>
#include <cuda_bf16.h>
#include <math.h>
#include <stdint.h>

#define N_NODES 100000
#define N_EDGES 600000
#define DIM     128
#define HEADS   2
#define NODE_TILES 1563   // ceil(100000/64)
#define EDGE_TILES 9375   // 600000/64
#define NODE_GROUPS 74    // CTAs per weight matrix
#define NODE_CTAS  (4 * NODE_GROUPS)   // 296
#define EDGE_CTAS  586
#define SROW    272       // smem row stride in bytes (136 bf16) — conflict-free ldmatrix
// smem offsets: A_h=0 (64 rows), A_l=17408, B_h=34816 (128 rows), B_l=69632
#define OFF_AL 17408u
#define OFF_BH 34816u
#define OFF_BL 69632u
#define SMEM_GEMM (OFF_BL + 128 * SROW)   // 104448 B -> 2 CTAs/SM

// ---------------- scratch (device globals; no runtime allocation) ----------
__device__ float g_q[(size_t)N_NODES * DIM];
__device__ float g_k[(size_t)N_NODES * DIM];
__device__ float g_v[(size_t)N_NODES * DIM];
__device__ float g_e[(size_t)N_EDGES * DIM];
__device__ float g_u[(size_t)N_NODES * DIM];     // unnormalized aggregation
__device__ float g_denom[(size_t)N_NODES * HEADS];
// pre-split weights, transposed to [n][k], bf16 pairs packed in uint32 (k-contiguous)
__device__ uint32_t g_Bh[5 * 8192];   // Wq,Wk,Wv,Wskip,We
__device__ uint32_t g_Bl[5 * 8192];

// ---------------- helpers ---------------------------------------------------
__device__ __forceinline__ void split_pack(float v0, float v1, uint32_t& hp, uint32_t& lp) {
    __nv_bfloat16 h0 = __float2bfloat16(v0), h1 = __float2bfloat16(v1);
    __nv_bfloat16 l0 = __float2bfloat16(v0 - __bfloat162float(h0));
    __nv_bfloat16 l1 = __float2bfloat16(v1 - __bfloat162float(h1));
    hp = ((uint32_t)__bfloat16_as_ushort(h1) << 16) | (uint32_t)__bfloat16_as_ushort(h0);
    lp = ((uint32_t)__bfloat16_as_ushort(l1) << 16) | (uint32_t)__bfloat16_as_ushort(l0);
}

__device__ __forceinline__ void ldsm_x4(uint32_t r[4], uint32_t addr) {
    asm volatile("ldmatrix.sync.aligned.m8n8.x4.shared.b16 {%0,%1,%2,%3}, [%4];"
                 : "=r"(r[0]), "=r"(r[1]), "=r"(r[2]), "=r"(r[3]) : "r"(addr));
}
__device__ __forceinline__ void mma_bf16(float c[4], const uint32_t a[4], const uint32_t b[2]) {
    asm volatile(
        "mma.sync.aligned.m16n8k16.row.col.f32.bf16.bf16.f32 "
        "{%0,%1,%2,%3}, {%4,%5,%6,%7}, {%8,%9}, {%0,%1,%2,%3};"
        : "+f"(c[0]), "+f"(c[1]), "+f"(c[2]), "+f"(c[3])
        : "r"(a[0]), "r"(a[1]), "r"(a[2]), "r"(a[3]), "r"(b[0]), "r"(b[1]));
}
__device__ __forceinline__ void red_add_v4(float* p, float4 v) {
    asm volatile("red.global.add.v4.f32 [%0], {%1,%2,%3,%4};"
                 :: "l"(p), "f"(v.x), "f"(v.y), "f"(v.z), "f"(v.w) : "memory");
}
__device__ __forceinline__ void red_add_v2(float* p, float a, float b) {
    asm volatile("red.global.add.v2.f32 [%0], {%1,%2};"
                 :: "l"(p), "f"(a), "f"(b) : "memory");
}

// accurate-enough cos: Cody-Waite range reduction + MUFU
__device__ __forceinline__ float cos_acc(float x) {
    float k = rintf(x * 0.15915494309189535f);
    float r = fmaf(k, -6.28125f, x);              // 2*pi = 6.28125 + 1.9353...e-3
    r = fmaf(k, -1.9353071795864769e-3f, r);
    return __cosf(r);
}

// Warp-level GEMM: D[64,128] = A[64,128] @ B[128,128]^T (B stored [n][k]).
// 8 warps: wm = wid>>1 in 0..3 -> rows wm*16..+16; wn = wid&1 -> cols wn*64..+64.
// acc[8][4]. B fragments loaded pairwise via ldmatrix.x4 (two n-frags per op).
#define GEMM_BODY(sbase, acc, lane, wm, wn)                                              \
    {                                                                                    \
        const uint32_t a_row = (uint32_t)(((wm) * 16 + ((lane) & 15)) * SROW             \
                                          + (((lane) >> 4) << 4));                       \
        const uint32_t b_row = (uint32_t)((((wn) * 64 + (((lane) >> 4) << 3)             \
                                          + ((lane) & 7)) * SROW)                        \
                                          + ((((lane) >> 3) & 1) << 4));                 \
        _Pragma("unroll")                                                                \
        for (int k0 = 0; k0 < 128; k0 += 16) {                                           \
            uint32_t ah[4], al[4];                                                       \
            ldsm_x4(ah, (sbase) + a_row + k0 * 2);                                       \
            ldsm_x4(al, (sbase) + OFF_AL + a_row + k0 * 2);                              \
            _Pragma("unroll")                                                            \
            for (int fp = 0; fp < 4; fp++) {                                             \
                uint32_t bo = b_row + (uint32_t)(fp * 16 * SROW) + (uint32_t)(k0 * 2);   \
                uint32_t bh[4], bl[4];                                                   \
                ldsm_x4(bh, (sbase) + OFF_BH + bo);                                      \
                ldsm_x4(bl, (sbase) + OFF_BL + bo);                                      \
                mma_bf16(acc[2 * fp],     ah, &bh[0]);                                   \
                mma_bf16(acc[2 * fp],     ah, &bl[0]);                                   \
                mma_bf16(acc[2 * fp],     al, &bh[0]);                                   \
                mma_bf16(acc[2 * fp + 1], ah, &bh[2]);                                   \
                mma_bf16(acc[2 * fp + 1], ah, &bl[2]);                                   \
                mma_bf16(acc[2 * fp + 1], al, &bh[2]);                                   \
            }                                                                            \
        }                                                                                \
    }

// ---------------- kernel Z: zero denominators + u accumulator --------------
__global__ void zero_kernel() {
    int i = blockIdx.x * blockDim.x + threadIdx.x;
    int stride = gridDim.x * blockDim.x;
    float4* u4 = (float4*)g_u;
    for (int j = i; j < N_NODES * DIM / 4; j += stride)
        u4[j] = make_float4(0.f, 0.f, 0.f, 0.f);
    for (int j = i; j < N_NODES * HEADS; j += stride) g_denom[j] = 0.0f;
}

// ---------------- conv_w: split + transpose 5 weight matrices --------------
__global__ void conv_w_kernel(const float* __restrict__ Wq, const float* __restrict__ Wk,
                              const float* __restrict__ Wv, const float* __restrict__ Wskip,
                              const float* __restrict__ We) {
    int idx = blockIdx.x * blockDim.x + threadIdx.x;
    if (idx >= 5 * 8192) return;
    const float* Ws[5] = {Wq, Wk, Wv, Wskip, We};
    int m  = idx >> 13;
    int n  = (idx >> 6) & 127;
    int kp = idx & 63;
    const float* W = Ws[m];
    float v0 = W[(2 * kp) * DIM + n];
    float v1 = W[(2 * kp + 1) * DIM + n];
    uint32_t hp, lp; split_pack(v0, v1, hp, lp);
    g_Bh[idx] = hp;   // [m][n][kp]
    g_Bl[idx] = lp;
}

// ---------------- fused GEMM: node q/k/v/skip + edge e ---------------------
__global__ void __launch_bounds__(256, 2)
gemm_fused_kernel(const float* __restrict__ x,
                  const float* __restrict__ bq, const float* __restrict__ bk,
                  const float* __restrict__ bv, const float* __restrict__ bskip,
                  float* __restrict__ out_skip,
                  const float* __restrict__ last_update, const int* __restrict__ edge_index,
                  const float* __restrict__ t, const float* __restrict__ msg,
                  const float* __restrict__ wt, const float* __restrict__ bt)
{
    extern __shared__ char sm[];
    __shared__ float s_rel[64];
    const uint32_t sbase = (uint32_t)__cvta_generic_to_shared(sm);
    const int tid  = threadIdx.x;
    const int lane = tid & 31, wid = tid >> 5;
    const int wm = wid >> 1, wn = wid & 1;

    if (blockIdx.x < NODE_CTAS) {
        // ---------------- node part ----------------
        const int m = blockIdx.x & 3;
        const int j = blockIdx.x >> 2;
        {
            const uint4* srcH = (const uint4*)&g_Bh[m * 8192];
            const uint4* srcL = (const uint4*)&g_Bl[m * 8192];
            for (int i = tid; i < 2048; i += 256) {
                int r = i >> 4, ch = i & 15;
                uint32_t off = (uint32_t)(r * SROW + ch * 16);
                *(uint4*)(sm + OFF_BH + off) = srcH[i];
                *(uint4*)(sm + OFF_BL + off) = srcL[i];
            }
        }
        const float* bias = (m == 0) ? bq : (m == 1) ? bk : (m == 2) ? bv : bskip;
        float* O = (m == 0) ? g_q : (m == 1) ? g_k : (m == 2) ? g_v : out_skip;

        for (int tile = j; tile < NODE_TILES; tile += NODE_GROUPS) {
            for (int idx = tid; idx < 64 * 32; idx += 256) {
                int r = idx >> 5, jj = idx & 31;
                int row = tile * 64 + r;
                float4 v = make_float4(0.f, 0.f, 0.f, 0.f);
                if (row < N_NODES) v = *(const float4*)&x[(size_t)row * DIM + jj * 4];
                uint32_t h0, l0, h1, l1;
                split_pack(v.x, v.y, h0, l0);
                split_pack(v.z, v.w, h1, l1);
                uint32_t off = (uint32_t)(r * SROW + jj * 8);
                *(uint2*)(sm + off)          = make_uint2(h0, h1);
                *(uint2*)(sm + OFF_AL + off) = make_uint2(l0, l1);
            }
            __syncthreads();

            float acc[8][4];
            #pragma unroll
            for (int b = 0; b < 8; b++)
                acc[b][0] = acc[b][1] = acc[b][2] = acc[b][3] = 0.f;
            GEMM_BODY(sbase, acc, lane, wm, wn);

            #pragma unroll
            for (int fn = 0; fn < 8; fn++) {
                int col = wn * 64 + fn * 8 + (lane & 3) * 2;
                float2 b2 = *(const float2*)&bias[col];
                int r0 = tile * 64 + wm * 16 + (lane >> 2);
                if (r0 < N_NODES) {
                    float2 o = make_float2(acc[fn][0] + b2.x, acc[fn][1] + b2.y);
                    *(float2*)&O[(size_t)r0 * DIM + col] = o;
                }
                int r1 = r0 + 8;
                if (r1 < N_NODES) {
                    float2 o = make_float2(acc[fn][2] + b2.x, acc[fn][3] + b2.y);
                    *(float2*)&O[(size_t)r1 * DIM + col] = o;
                }
            }
            __syncthreads();   // all A readers done before next overwrite
        }
    } else {
        // ---------------- edge part ----------------
        const int j = blockIdx.x - NODE_CTAS;
        const int* src = edge_index;
        {
            const uint4* srcH = (const uint4*)&g_Bh[4 * 8192];
            const uint4* srcL = (const uint4*)&g_Bl[4 * 8192];
            for (int i = tid; i < 2048; i += 256) {
                int r = i >> 4, ch = i & 15;
                uint32_t off = (uint32_t)(r * SROW + ch * 16);
                *(uint4*)(sm + OFF_BH + off) = srcH[i];
                *(uint4*)(sm + OFF_BL + off) = srcL[i];
            }
        }

        for (int tile = j; tile < EDGE_TILES; tile += EDGE_CTAS) {
            const int e0 = tile * 64;
            if (tid < 64) {
                int e = e0 + tid;
                s_rel[tid] = last_update[src[e]] - t[e];
            }
            __syncthreads();

            for (int idx = tid; idx < 64 * 32; idx += 256) {
                int i = idx >> 5, jj = idx & 31;
                int c0 = jj * 4;
                int e = e0 + i;
                float v0, v1, v2, v3;
                if (c0 < 64) {
                    float r = s_rel[i];
                    v0 = cos_acc(fmaf(r, wt[c0],     bt[c0]));
                    v1 = cos_acc(fmaf(r, wt[c0 + 1], bt[c0 + 1]));
                    v2 = cos_acc(fmaf(r, wt[c0 + 2], bt[c0 + 2]));
                    v3 = cos_acc(fmaf(r, wt[c0 + 3], bt[c0 + 3]));
                } else {
                    float4 mv = *(const float4*)&msg[(size_t)e * 64 + (c0 - 64)];
                    v0 = mv.x; v1 = mv.y; v2 = mv.z; v3 = mv.w;
                }
                uint32_t h0, l0, h1, l1;
                split_pack(v0, v1, h0, l0);
                split_pack(v2, v3, h1, l1);
                uint32_t off = (uint32_t)(i * SROW + jj * 8);
                *(uint2*)(sm + off)          = make_uint2(h0, h1);
                *(uint2*)(sm + OFF_AL + off) = make_uint2(l0, l1);
            }
            __syncthreads();

            float acc[8][4];
            #pragma unroll
            for (int b = 0; b < 8; b++)
                acc[b][0] = acc[b][1] = acc[b][2] = acc[b][3] = 0.f;
            GEMM_BODY(sbase, acc, lane, wm, wn);

            #pragma unroll
            for (int fn = 0; fn < 8; fn++) {
                int col = wn * 64 + fn * 8 + (lane & 3) * 2;
                int r0 = e0 + wm * 16 + (lane >> 2);
                float2 o0 = make_float2(acc[fn][0], acc[fn][1]);
                *(float2*)&g_e[(size_t)r0 * DIM + col] = o0;
                float2 o1 = make_float2(acc[fn][2], acc[fn][3]);
                *(float2*)&g_e[(size_t)(r0 + 8) * DIM + col] = o1;
            }
            __syncthreads();   // readers of s_rel / A done before next overwrite
        }
    }
}

// ---------------- edge_attn: logits + exp + unnormalized scatter -----------
// out[d] = (sum_e ex*(v+e)) / denom[d]  -- normalization deferred to finalize.
// Half-warp xor-reduce leaves each head's full dot broadcast in all 16 lanes,
// so every lane already holds the correct ex for its own columns.
__global__ void __launch_bounds__(256)
edge_attn_kernel(const int* __restrict__ edge_index)
{
    const int lane = threadIdx.x & 31;
    const int warp = (blockIdx.x * blockDim.x + threadIdx.x) >> 5;
    const int nwarps = (gridDim.x * blockDim.x) >> 5;
    const int* src = edge_index;
    const int* dst = edge_index + N_EDGES;

    for (int e = warp; e < N_EDGES; e += nwarps) {
        int s = src[e], d = dst[e];
        int c = lane * 4;
        float4 q  = *(const float4*)&g_q[(size_t)d * DIM + c];
        float4 k  = *(const float4*)&g_k[(size_t)s * DIM + c];
        float4 ee = *(const float4*)&g_e[(size_t)e * DIM + c];
        float4 vv = *(const float4*)&g_v[(size_t)s * DIM + c];
        float dot = q.x * (k.x + ee.x) + q.y * (k.y + ee.y)
                  + q.z * (k.z + ee.z) + q.w * (k.w + ee.w);
        #pragma unroll
        for (int o = 8; o > 0; o >>= 1) dot += __shfl_xor_sync(0xffffffffu, dot, o);
        float ex = expf(dot * 0.125f);                     // / sqrt(64); per-head, all lanes
        float ex1 = __shfl_sync(0xffffffffu, ex, 16);      // head1 value to lane 0
        if (lane == 0) red_add_v2(&g_denom[(size_t)d * 2], ex, ex1);
        float4 u = make_float4(ex * (vv.x + ee.x), ex * (vv.y + ee.y),
                               ex * (vv.z + ee.z), ex * (vv.w + ee.w));
        red_add_v4(&g_u[(size_t)d * DIM + c], u);
    }
}

// ---------------- finalize: out += u / denom -------------------------------
__global__ void __launch_bounds__(256)
finalize_kernel(float* __restrict__ out)
{
    int i = blockIdx.x * blockDim.x + threadIdx.x;
    int stride = gridDim.x * blockDim.x;
    for (int j = i; j < N_NODES * 32; j += stride) {
        int row = j >> 5;
        int cq  = j & 31;            // quad index; head = cq>=16
        float den = g_denom[row * 2 + (cq >> 4)] + 1e-16f;
        float inv = 1.0f / den;
        float4 u = *(const float4*)&g_u[(size_t)row * DIM + cq * 4];
        float* op = &out[(size_t)row * DIM + cq * 4];
        float4 o = *(const float4*)op;
        o.x += u.x * inv; o.y += u.y * inv; o.z += u.z * inv; o.w += u.w * inv;
        *(float4*)op = o;
    }
}

// ---------------- launch ----------------------------------------------------
extern "C" void kernel_launch(void* const* d_in, const int* in_sizes, int n_in,
                              void* d_out, int out_size)
{
    const float* x           = (const float*)d_in[0];
    const float* last_update = (const float*)d_in[1];
    const int*   edge_index  = (const int*)  d_in[2];
    const float* t           = (const float*)d_in[3];
    const float* msg         = (const float*)d_in[4];
    const float* wt          = (const float*)d_in[5];
    const float* bt          = (const float*)d_in[6];
    const float* Wq          = (const float*)d_in[7];
    const float* bq          = (const float*)d_in[8];
    const float* Wk          = (const float*)d_in[9];
    const float* bk          = (const float*)d_in[10];
    const float* Wv          = (const float*)d_in[11];
    const float* bv          = (const float*)d_in[12];
    const float* We          = (const float*)d_in[13];
    const float* Wskip       = (const float*)d_in[14];
    const float* bskip       = (const float*)d_in[15];
    float* out = (float*)d_out;

    cudaFuncSetAttribute(gemm_fused_kernel,
                         cudaFuncAttributeMaxDynamicSharedMemorySize, SMEM_GEMM);

    zero_kernel<<<1024, 256>>>();
    conv_w_kernel<<<(5 * 8192 + 255) / 256, 256>>>(Wq, Wk, Wv, Wskip, We);

    gemm_fused_kernel<<<NODE_CTAS + EDGE_CTAS, 256, SMEM_GEMM>>>(
        x, bq, bk, bv, bskip, out,
        last_update, edge_index, t, msg, wt, bt);

    edge_attn_kernel<<<2048, 256>>>(edge_index);
    finalize_kernel<<<2048, 256>>>(out);
}